// round 6
// baseline (speedup 1.0000x reference)
#include <cuda_runtime.h>
#include <cuda_bf16.h>

constexpr int N_NODES = 100000;
constexpr int N_EDGES = 3200000;
constexpr int F   = 32;
constexpr int L   = 50;
constexpr int EL  = 10;
constexpr int K   = 16;
constexpr int CAP = 96;   // ELL capacity (max degree ~60 for Poisson(32)); mult of 8

// Persistent scratch (static device arrays; zero-initialized at load).
// ELL slots beyond cnt[n] are NEVER written -> remain {0,0,0,0}: weight 0.0
// (contributes nothing), byte-offset 0 (harmless gather of row 0).
__device__ int            g_cnt[N_NODES];
__device__ unsigned char  g_lbl8[N_NODES];
// per-edge record: { src*64 (byte offset), W1 bits, W2 bits, W3 bits }
__device__ uint4          g_equad[(size_t)N_NODES * CAP];
__device__ unsigned       g_xb[(size_t)N_NODES * (F / 2)]; // bf16x2 rows (64B/row)
__device__ unsigned       g_hA[(size_t)N_NODES * (F / 2)];
__device__ unsigned       g_hB[(size_t)N_NODES * (F / 2)];
__device__ float          g_sums[L * F];                   // zeroed by final_head

// ---------------------------------------------------------------------------
__global__ __launch_bounds__(256)
void prep_nodes(const int* __restrict__ lbl)
{
    int i = blockIdx.x * blockDim.x + threadIdx.x;
    if (i < N_NODES) {
        g_lbl8[i] = (unsigned char)lbl[i];
        g_cnt[i]  = 0;
    }
}

__global__ __launch_bounds__(256)
void x_to_bf16(const float* __restrict__ x)
{
    int i = blockIdx.x * blockDim.x + threadIdx.x;   // over N*F/2
    if (i < N_NODES * (F / 2)) {
        __nv_bfloat162 h2 = __floats2bfloat162_rn(x[2 * i], x[2 * i + 1]);
        g_xb[i] = *reinterpret_cast<unsigned*>(&h2);
    }
}

// ---------------------------------------------------------------------------
// build ELL with baked per-layer weights
// ---------------------------------------------------------------------------
__global__ __launch_bounds__(256)
void build_ell(const int* __restrict__ esrc,
               const int* __restrict__ edst,
               const int* __restrict__ elab,
               const float* __restrict__ W1,
               const float* __restrict__ W2,
               const float* __restrict__ W3)
{
    int e = blockIdx.x * blockDim.x + threadIdx.x;
    if (e >= N_EDGES) return;
    int s = esrc[e];
    int d = edst[e];
    unsigned ls = g_lbl8[s];
    unsigned ld = g_lbl8[d];
    unsigned widx = (ls * L + ld) * EL + (unsigned)elab[e];
    int pos = atomicAdd(&g_cnt[d], 1);
    uint4 r;
    r.x = (unsigned)s * 64u;                 // byte offset of source row
    r.y = __float_as_uint(__ldg(&W1[widx]));
    r.z = __float_as_uint(__ldg(&W2[widx]));
    r.w = __float_as_uint(__ldg(&W3[widx]));
    g_equad[(size_t)d * CAP + pos] = r;
}

// ---------------------------------------------------------------------------
// Node accumulation: 4 edges per group, 8 lanes per edge, 2 groups unrolled.
// lane = 8*g + c ; returns per-lane partial float4 (features [4c,4c+4)).
// LAYER selects which baked weight to use.
// ---------------------------------------------------------------------------
template<int LAYER>
__device__ __forceinline__
float4 node_acc4(const unsigned* __restrict__ x_in,
                 const uint4*    __restrict__ edata,
                 int cnt, int g, int c)
{
    const char* xb = (const char*)x_in + c * 8;   // per-lane base
    float4 acc = make_float4(0.f, 0.f, 0.f, 0.f);
    int cnt_r = (cnt + 7) & ~7;                   // padded slots are zero-weight
    for (int j = 0; j < cnt_r; j += 8) {
        uint4 r0 = __ldg(&edata[j + g]);
        uint4 r1 = __ldg(&edata[j + 4 + g]);
        float w0 = __uint_as_float(LAYER == 0 ? r0.y : LAYER == 1 ? r0.z : r0.w);
        float w1 = __uint_as_float(LAYER == 0 ? r1.y : LAYER == 1 ? r1.z : r1.w);
        uint2 a0 = __ldg(reinterpret_cast<const uint2*>(xb + r0.x));
        uint2 a1 = __ldg(reinterpret_cast<const uint2*>(xb + r1.x));
        acc.x = fmaf(w0, __uint_as_float(a0.x << 16),         acc.x);
        acc.y = fmaf(w0, __uint_as_float(a0.x & 0xFFFF0000u), acc.y);
        acc.z = fmaf(w0, __uint_as_float(a0.y << 16),         acc.z);
        acc.w = fmaf(w0, __uint_as_float(a0.y & 0xFFFF0000u), acc.w);
        acc.x = fmaf(w1, __uint_as_float(a1.x << 16),         acc.x);
        acc.y = fmaf(w1, __uint_as_float(a1.x & 0xFFFF0000u), acc.y);
        acc.z = fmaf(w1, __uint_as_float(a1.y << 16),         acc.z);
        acc.w = fmaf(w1, __uint_as_float(a1.y & 0xFFFF0000u), acc.w);
    }
    return acc;
}

__device__ __forceinline__
float4 reduce_groups(float4 a)
{
    #pragma unroll
    for (int m = 8; m <= 16; m <<= 1) {
        a.x += __shfl_xor_sync(0xffffffffu, a.x, m);
        a.y += __shfl_xor_sync(0xffffffffu, a.y, m);
        a.z += __shfl_xor_sync(0xffffffffu, a.z, m);
        a.w += __shfl_xor_sync(0xffffffffu, a.w, m);
    }
    return a;
}

// ---------------------------------------------------------------------------
// conv layers 1,2
// ---------------------------------------------------------------------------
template<int LAYER>
__global__ __launch_bounds__(256)
void conv_ell(const unsigned* __restrict__ x_in,
              unsigned*       __restrict__ h_out,
              const float* __restrict__ b)
{
    int n    = (blockIdx.x * blockDim.x + threadIdx.x) >> 5;
    int lane = threadIdx.x & 31;
    if (n >= N_NODES) return;
    int g = lane >> 3, c = lane & 7;

    int cnt = __ldg(&g_cnt[n]);
    float4 acc = node_acc4<LAYER>(x_in, &g_equad[(size_t)n * CAP], cnt, g, c);
    acc = reduce_groups(acc);

    if (g == 0) {
        float bias = b[g_lbl8[n]];
        __nv_bfloat162 p0 = __floats2bfloat162_rn(tanhf(acc.x + bias), tanhf(acc.y + bias));
        __nv_bfloat162 p1 = __floats2bfloat162_rn(tanhf(acc.z + bias), tanhf(acc.w + bias));
        uint2 st;
        st.x = *reinterpret_cast<unsigned*>(&p0);
        st.y = *reinterpret_cast<unsigned*>(&p1);
        reinterpret_cast<uint2*>(h_out)[(size_t)n * 8 + c] = st;
    }
}

// ---------------------------------------------------------------------------
// conv layer 3 fused with label pooling
// ---------------------------------------------------------------------------
__global__ __launch_bounds__(256)
void conv_ell_pool(const unsigned* __restrict__ x_in,
                   const float* __restrict__ b)
{
    __shared__ float pool[L * F];
    for (int i = threadIdx.x; i < L * F; i += blockDim.x) pool[i] = 0.0f;
    __syncthreads();

    int lane = threadIdx.x & 31;
    int g = lane >> 3, c = lane & 7;
    int wpb = blockDim.x >> 5;
    int n0  = blockIdx.x * wpb + (threadIdx.x >> 5);
    int ns  = gridDim.x * wpb;

    for (int n = n0; n < N_NODES; n += ns) {
        int cnt = __ldg(&g_cnt[n]);
        float4 acc = node_acc4<2>(x_in, &g_equad[(size_t)n * CAP], cnt, g, c);
        acc = reduce_groups(acc);
        if (g == 0) {
            int   l    = g_lbl8[n];
            float bias = b[l];
            atomicAdd(&pool[l * F + 4 * c + 0], tanhf(acc.x + bias));
            atomicAdd(&pool[l * F + 4 * c + 1], tanhf(acc.y + bias));
            atomicAdd(&pool[l * F + 4 * c + 2], tanhf(acc.z + bias));
            atomicAdd(&pool[l * F + 4 * c + 3], tanhf(acc.w + bias));
        }
    }
    __syncthreads();

    for (int i = threadIdx.x; i < L * F; i += blockDim.x)
        atomicAdd(&g_sums[i], pool[i]);
}

// ---------------------------------------------------------------------------
__global__ __launch_bounds__(512)
void final_head(const float* __restrict__ Wr,
                const float* __restrict__ br,
                float* __restrict__ out)
{
    __shared__ float red[512];
    int t = threadIdx.x;
    int k = t & 15;
    int chunk = t >> 4;

    float acc = 0.0f;
    for (int i = chunk; i < L * F; i += 32)
        acc += g_sums[i] * Wr[i * K + k];
    red[t] = acc;
    __syncthreads();

    #pragma unroll
    for (int s = 256; s >= 16; s >>= 1) {
        if (t < s) red[t] += red[t + s];
        __syncthreads();
    }
    if (t < K) out[t] = tanhf(red[t] + br[t]);
    __syncthreads();

    for (int i = t; i < L * F; i += 512) g_sums[i] = 0.0f;   // reset invariant
}

// ---------------------------------------------------------------------------
// inputs: 0:x 1:W1 2:b1 3:W2 4:b2 5:W3 6:b3 7:Wr 8:br 9:node_labels
//         10:edge_src 11:edge_dst 12:edge_labels
// ---------------------------------------------------------------------------
extern "C" void kernel_launch(void* const* d_in, const int* in_sizes, int n_in,
                              void* d_out, int out_size)
{
    const float* x   = (const float*)d_in[0];
    const float* W1  = (const float*)d_in[1];
    const float* b1  = (const float*)d_in[2];
    const float* W2  = (const float*)d_in[3];
    const float* b2  = (const float*)d_in[4];
    const float* W3  = (const float*)d_in[5];
    const float* b3  = (const float*)d_in[6];
    const float* Wr  = (const float*)d_in[7];
    const float* br  = (const float*)d_in[8];
    const int* lbl   = (const int*)d_in[9];
    const int* esrc  = (const int*)d_in[10];
    const int* edst  = (const int*)d_in[11];
    const int* elab  = (const int*)d_in[12];
    float* out = (float*)d_out;

    unsigned *xb, *hA, *hB;
    cudaGetSymbolAddress((void**)&xb, g_xb);
    cudaGetSymbolAddress((void**)&hA, g_hA);
    cudaGetSymbolAddress((void**)&hB, g_hB);

    const int ng = (N_NODES + 255) / 256;            // 391
    const int pg = (N_NODES * (F / 2) + 255) / 256;  // 6250
    const int eg = (N_EDGES + 255) / 256;            // 12500
    const int cg = (N_NODES * 32 + 255) / 256;       // warp per node

    prep_nodes<<<ng, 256>>>(lbl);
    x_to_bf16<<<pg, 256>>>(x);
    build_ell<<<eg, 256>>>(esrc, edst, elab, W1, W2, W3);

    conv_ell<0><<<cg, 256>>>(xb, hA, b1);
    conv_ell<1><<<cg, 256>>>(hA, hB, b2);
    conv_ell_pool<<<1184, 256>>>(hB, b3);

    final_head<<<1, 512>>>(Wr, br, out);
}